// round 17
// baseline (speedup 1.0000x reference)
#include <cuda_runtime.h>
#include <cstdint>

// CarryLSTMModel: B=8192, T=1024, D=16, H=16 (4H=64 gates, order i,f,g,o)
// fp16 m16n8k16, M=4 elems/warp -> 2048 warps (3.5/SMSP):
//   A rows r hold elem r mod 4 (4x duplication; a1=a0, a3=a2).
//   16 mmas/warp-step; duplicate lanes (gid vs gid+4) hold identical z,
//   so activations are SPLIT: lane gid handles gate-pair gj = gid>>2 only
//   (10 MUFU/lane-step; chip MUFU floor unchanged at ~300us).
//   LDS from row gid&3, RS=24: conflict-free per 16-word phase (verified).
//   Weights pre-scaled (0.5 i/f/o, 1 g): sig(z)=0.5+0.5*tanh(z/2), MUFU.TANH.
//   x fp32 in smem via 4-slot cp.async ring (1 cp16/lane, lanes<16);
//   h fp32 double-buffered smem; f16x2 conversion on load.

#define NB 8192
#define NT 1024
#define ND 16
#define NG 64
#define RS 24                  // padded row stride (floats)
#define XSLOT (4 * RS * 4)     // 384 B per 4x16 fp32 tile

typedef unsigned int u32;

__device__ __forceinline__ u32 smem_u32(const void* p) {
    return (u32)__cvta_generic_to_shared(p);
}
__device__ __forceinline__ float tanhap(float x) {
    float r; asm("tanh.approx.f32 %0, %1;" : "=f"(r) : "f"(x)); return r;
}
__device__ __forceinline__ float ex2f(float x) {
    float r; asm("ex2.approx.f32 %0, %1;" : "=f"(r) : "f"(x)); return r;
}
__device__ __forceinline__ float rcpf(float x) {
    float r; asm("rcp.approx.f32 %0, %1;" : "=f"(r) : "f"(x)); return r;
}
// pack two f32 -> f16x2 (lo = first arg)
__device__ __forceinline__ u32 pkh2(float lo, float hi) {
    u32 r; asm("cvt.rn.f16x2.f32 %0, %1, %2;" : "=r"(r) : "f"(hi), "f"(lo)); return r;
}
__device__ __forceinline__ void lds64(u32 a, float& x, float& y) {
    asm volatile("ld.shared.v2.f32 {%0, %1}, [%2];" : "=f"(x), "=f"(y) : "r"(a));
}
__device__ __forceinline__ void sts64(u32 a, float x, float y) {
    asm volatile("st.shared.v2.f32 [%0], {%1, %2};" :: "r"(a), "f"(x), "f"(y) : "memory");
}
__device__ __forceinline__ void cp16(u32 d, const float* s) {
    asm volatile("cp.async.ca.shared.global [%0], [%1], 16;" :: "r"(d), "l"(s) : "memory");
}
__device__ __forceinline__ void cp_commit() {
    asm volatile("cp.async.commit_group;" ::: "memory");
}
// D = A(f16 m16k16) @ B(f16 k16n8) + C(f32)
__device__ __forceinline__ void mma16(float& d0, float& d1, float& d2, float& d3,
                                      u32 a0, u32 a1, u32 a2, u32 a3,
                                      u32 b0, u32 b1,
                                      float c0, float c1, float c2, float c3)
{
    asm volatile("mma.sync.aligned.m16n8k16.row.col.f32.f16.f16.f32 "
        "{%0,%1,%2,%3}, {%4,%5,%6,%7}, {%8,%9}, {%10,%11,%12,%13};"
        : "=f"(d0), "=f"(d1), "=f"(d2), "=f"(d3)
        : "r"(a0), "r"(a1), "r"(a2), "r"(a3), "r"(b0), "r"(b1),
          "f"(c0), "f"(c1), "f"(c2), "f"(c3));
}

__global__ __launch_bounds__(128)
void lstm_mma_kernel(const float* __restrict__ x,
                     const float* __restrict__ Wi,
                     const float* __restrict__ Wh,
                     const float* __restrict__ bias,
                     const float* __restrict__ Wd,
                     const float* __restrict__ bd,
                     float* __restrict__ out)
{
    __shared__ __align__(16) float xsm[4][4][4 * RS];   // [warp][slot] x ring
    __shared__ __align__(16) float hsm[4][2][4 * RS];   // [warp][buf]  h

    const int wib  = threadIdx.x >> 5;
    const int lane = threadIdx.x & 31;
    const int gid  = lane >> 2;      // 0..7
    const int tig  = lane & 3;
    const int er   = gid & 3;        // this lane's elem row (0..3)
    const int gj   = gid >> 2;       // gate-pair this lane activates (0/1)
    const int e0   = blockIdx.x * 16 + wib * 4;   // warp's 4 elements

    // ---- B fragments (f16x2, pre-scaled) + bias C-init ----
    u32 Bx[8][2], Bh[8][2];
    float bc0[8], bc1[8];
#pragma unroll
    for (int g = 0; g < 8; ++g) {
        const int n = 8 * g + gid;
        const float sc = (n < 32 || n >= 48) ? 0.5f : 1.0f;
        Bx[g][0] = pkh2(Wi[(2*tig)     * NG + n] * sc, Wi[(2*tig + 1) * NG + n] * sc);
        Bx[g][1] = pkh2(Wi[(2*tig + 8) * NG + n] * sc, Wi[(2*tig + 9) * NG + n] * sc);
        Bh[g][0] = pkh2(Wh[(2*tig)     * NG + n] * sc, Wh[(2*tig + 1) * NG + n] * sc);
        Bh[g][1] = pkh2(Wh[(2*tig + 8) * NG + n] * sc, Wh[(2*tig + 9) * NG + n] * sc);
        const int n0 = 8 * g + 2 * tig;
        bc0[g] = bias[n0]     * sc;
        bc1[g] = bias[n0 + 1] * sc;
    }

    const u32 xbase = smem_u32(&xsm[wib][0][0]);
    const u32 hbase = smem_u32(&hsm[wib][0][0]);
    const u32 laneA = (u32)((er * RS + 2 * tig) * 4);              // A pair; +32B = k+8
    const u32 hwb   = hbase + (u32)((er * RS + 8 * gj + 2 * tig) * 4);  // h write

    // x fetch (lanes 0-15): elem (lane>>2)&3, quarter lane&3 (4 floats)
    const float* xg0 = x + (size_t)(e0 + ((lane >> 2) & 3)) * (NT * ND) + (lane & 3) * 4;
    const u32 xfd = xbase + (u32)((((lane >> 2) & 3) * RS + (lane & 3) * 4) * 4);
    const bool fl = (lane < 16);

    // h(0) = 0 in buffer 0 (32 lanes x sts64 = 64 floats, full tile)
    sts64(hwb, 0.f, 0.f);

    // prologue: x(0) -> slot 0, x(1) -> slot 1
    if (fl) cp16(xfd, xg0);
    cp_commit();
    if (fl) cp16(xfd + XSLOT, xg0 + ND);
    cp_commit();

    float cst[2] = {0.f, 0.f};

    // one step; s = t & 7. mode: 0 fetch+wait1, 1 wait0, 2 none.
    auto step = [&](int s, int mode, const float* xgp) {
        if (mode == 0) {
            const int ds = (s + 2) & 3;
            if (fl) cp16(xfd + (u32)(ds * XSLOT), xgp + s * ND);
            cp_commit();
            asm volatile("cp.async.wait_group 1;" ::: "memory");
        } else if (mode == 1) {
            asm volatile("cp.async.wait_group 0;" ::: "memory");
        }
        __syncwarp();

        // A fragments (f32 -> f16x2); all rows duplicate row er
        const u32 xb = xbase + (u32)((s & 3) * XSLOT) + laneA;
        const u32 hb = hbase + (u32)((s & 1) * XSLOT) + laneA;
        float t0, t1;
        lds64(xb + 0,  t0, t1);  const u32 ax0 = pkh2(t0, t1);
        lds64(xb + 32, t0, t1);  const u32 ax2 = pkh2(t0, t1);
        lds64(hb + 0,  t0, t1);  const u32 ah0 = pkh2(t0, t1);
        lds64(hb + 32, t0, t1);  const u32 ah2 = pkh2(t0, t1);

        // z = x@Wi + h@Wh + b; 2 chained mma per gate-group, keep d0,d1
        float z[8][2];
#pragma unroll
        for (int g = 0; g < 8; ++g) {
            float d0, d1, d2, d3;
            mma16(d0, d1, d2, d3, ax0, ax0, ax2, ax2,
                  Bx[g][0], Bx[g][1], bc0[g], bc1[g], bc0[g], bc1[g]);
            mma16(d0, d1, d2, d3, ah0, ah0, ah2, ah2,
                  Bh[g][0], Bh[g][1], d0, d1, d2, d3);
            z[g][0] = d0; z[g][1] = d1;
        }

        // activations: this lane handles ONLY gate-pair gj (duplicate lane
        // gid^4 handles the other pair) -> 2 (e,j) tuples, 10 MUFU.
        const u32 hw = hwb + (u32)(((s & 1) ^ 1) * XSLOT);
        float hv[2];
#pragma unroll
        for (int cs = 0; cs < 2; ++cs) {
            float vI = fmaf(0.5f, tanhap(z[gj    ][cs]), 0.5f);
            float vF = fmaf(0.5f, tanhap(z[gj + 2][cs]), 0.5f);
            float vG = tanhap(z[gj + 4][cs]);
            float vO = fmaf(0.5f, tanhap(z[gj + 6][cs]), 0.5f);
            cst[cs] = fmaf(vF, cst[cs], vI * vG);
            hv[cs]  = vO * tanhap(cst[cs]);
        }
        sts64(hw, hv[0], hv[1]);   // h[er][8*gj + 2*tig + {0,1}]
    };

    const float* xg = xg0 + 2 * ND;   // source base: x(tb + 2 + s)

#pragma unroll 1
    for (int tb = 0; tb < NT - 8; tb += 8) {
#pragma unroll
        for (int s = 0; s < 8; ++s)
            step(s, 0, xg);
        xg += 8 * ND;
    }
    // final block: fetch while t+2 <= 1023, then drain
#pragma unroll
    for (int s = 0; s < 8; ++s)
        step(s, (s < 6) ? 0 : ((s == 6) ? 1 : 2), xg);

    // ---- head: logits = c_T @ Wd + bd, softmax(2) ----
    // lane holds c for (e = e0+er, j = 8*gj + 2*tig + cs). 8 lanes per elem
    // ({gid, gid+4} x tig): reduce over xor 1, 2, 16.
    float p0 = 0.f, p1 = 0.f;
#pragma unroll
    for (int cs = 0; cs < 2; ++cs) {
        const int jj = 8 * gj + 2 * tig + cs;
        p0 += cst[cs] * Wd[jj * 2];
        p1 += cst[cs] * Wd[jj * 2 + 1];
    }
#pragma unroll
    for (int off = 1; off <= 2; off <<= 1) {
        p0 += __shfl_xor_sync(0xffffffffu, p0, off);
        p1 += __shfl_xor_sync(0xffffffffu, p1, off);
    }
    p0 += __shfl_xor_sync(0xffffffffu, p0, 16);
    p1 += __shfl_xor_sync(0xffffffffu, p1, 16);
    if (tig == 0 && gj == 0) {
        const float L2E = 1.44269504088896340736f;
        const int e = e0 + er;
        float l0 = p0 + bd[0];
        float l1 = p1 + bd[1];
        float mx = fmaxf(l0, l1);
        float q0 = ex2f((l0 - mx) * L2E);
        float q1 = ex2f((l1 - mx) * L2E);
        float inv = rcpf(q0 + q1);
        out[2 * e]     = q0 * inv;
        out[2 * e + 1] = q1 * inv;
    }
}

extern "C" void kernel_launch(void* const* d_in, const int* in_sizes, int n_in,
                              void* d_out, int out_size)
{
    const float* x  = (const float*)d_in[0];
    const float* Wi = (const float*)d_in[1];
    const float* Wh = (const float*)d_in[2];
    const float* b  = (const float*)d_in[3];
    const float* Wd = (const float*)d_in[4];
    const float* bd = (const float*)d_in[5];
    float* out = (float*)d_out;

    lstm_mma_kernel<<<NB / 16, 128>>>(x, Wi, Wh, b, Wd, bd, out);
}